// round 16
// baseline (speedup 1.0000x reference)
#include <cuda_runtime.h>
#include <cuda_fp16.h>
#include <cstdint>

// Problem constants
#define BB 4
#define SS 2048
#define DD 1024
#define HH 16
#define HD 64
#define MM (BB * SS)   // 8192 rows

// ---------------- scratch (device globals; allocation-free rule) ----------------
__device__ __half g_q[MM * DD];       // Q fp16, pre-scaled by 0.125*log2e
__device__ __half g_k[MM * DD];
__device__ __half g_v[MM * DD];
__device__ __half g_x[MM * DD];
__device__ __half g_oa[MM * DD];

__device__ __half g_wq[DD * DD];      // transposed [n][k]
__device__ __half g_wk[DD * DD];
__device__ __half g_wv[DD * DD];
__device__ __half g_wo[DD * DD];      // row-major Wo == [n][k]

// [0..63] q m-tiles (target 8), [64..127] k+v m-tiles (target 16), [128..191] oa (target 16)
__device__ int g_cnt[192];

#define QSCALE (0.125f * 1.4426950408889634f)

// ---------------- PTX helpers ----------------
__device__ __forceinline__ uint32_t smem_u32(const void* p) {
    uint32_t a;
    asm("{ .reg .u64 t; cvta.to.shared.u64 t, %1; cvt.u32.u64 %0, t; }" : "=r"(a) : "l"(p));
    return a;
}
__device__ __forceinline__ void cp16(uint32_t dst, const void* src) {
    asm volatile("cp.async.cg.shared.global [%0], [%1], 16;" :: "r"(dst), "l"(src) : "memory");
}
#define CP_COMMIT() asm volatile("cp.async.commit_group;" ::: "memory")
#define CP_WAIT(n) asm volatile("cp.async.wait_group %0;" :: "n"(n) : "memory")

__device__ __forceinline__ void ldm4(uint32_t* d, uint32_t addr) {
    asm volatile("ldmatrix.sync.aligned.m8n8.x4.shared.b16 {%0,%1,%2,%3}, [%4];"
                 : "=r"(d[0]), "=r"(d[1]), "=r"(d[2]), "=r"(d[3]) : "r"(addr));
}
__device__ __forceinline__ void ldm4t(uint32_t* d, uint32_t addr) {
    asm volatile("ldmatrix.sync.aligned.m8n8.x4.trans.shared.b16 {%0,%1,%2,%3}, [%4];"
                 : "=r"(d[0]), "=r"(d[1]), "=r"(d[2]), "=r"(d[3]) : "r"(addr));
}
__device__ __forceinline__ void mma16816(float* c, const uint32_t* a, uint32_t b0, uint32_t b1) {
    asm volatile(
        "mma.sync.aligned.m16n8k16.row.col.f32.f16.f16.f32 "
        "{%0,%1,%2,%3}, {%4,%5,%6,%7}, {%8,%9}, {%0,%1,%2,%3};"
        : "+f"(c[0]), "+f"(c[1]), "+f"(c[2]), "+f"(c[3])
        : "r"(a[0]), "r"(a[1]), "r"(a[2]), "r"(a[3]), "r"(b0), "r"(b1));
}
__device__ __forceinline__ float ex2f(float x) {
    float r;
    asm("ex2.approx.f32 %0, %1;" : "=f"(r) : "f"(x));
    return r;
}
__device__ __forceinline__ uint32_t pack_h2(float x, float y) {
    __half2 h = __floats2half2_rn(x, y);
    return *(uint32_t*)&h;
}
__device__ __forceinline__ void spin_until(int* p, int target) {
    while (atomicAdd(p, 0) < target)
        __nanosleep(128);
}

// ---------------- fused prep kernel ----------------
// bids [0,8192): convert x.  [8192,9216): convert Wo.  [9216,12288): transpose Wq/Wk/Wv.
__global__ void __launch_bounds__(256)
prep_kernel(const float* __restrict__ x, const float* __restrict__ Wq,
            const float* __restrict__ Wk, const float* __restrict__ Wv,
            const float* __restrict__ Wo) {
    const int bid = blockIdx.x;
    if (bid == 0 && threadIdx.x < 192) g_cnt[threadIdx.x] = 0;

    if (bid < 9216) {
        const float* src = (bid < 8192) ? x : Wo;
        __half* dst = (bid < 8192) ? g_x : g_wo;
        int i = ((bid < 8192) ? bid : (bid - 8192)) * 256 + threadIdx.x;
        float4 v = ((const float4*)src)[i];
        ushort4 o;
        o.x = __half_as_ushort(__float2half_rn(v.x));
        o.y = __half_as_ushort(__float2half_rn(v.y));
        o.z = __half_as_ushort(__float2half_rn(v.z));
        o.w = __half_as_ushort(__float2half_rn(v.w));
        ((ushort4*)dst)[i] = o;
    } else {
        int t = bid - 9216;                 // 0..3071
        int z = t >> 10;
        int rem = t & 1023;
        int bx = rem & 31, by = rem >> 5;
        const float* W = (z == 0) ? Wq : ((z == 1) ? Wk : Wv);
        __half* dst = (z == 0) ? g_wq : ((z == 1) ? g_wk : g_wv);
        __shared__ float tt[32][33];
        int tx = threadIdx.x & 31;
        int ty = threadIdx.x >> 5;
        int k0 = by * 32;
        int n0 = bx * 32;
#pragma unroll
        for (int i = 0; i < 4; i++)
            tt[ty + i * 8][tx] = W[(size_t)(k0 + ty + i * 8) * DD + n0 + tx];
        __syncthreads();
#pragma unroll
        for (int i = 0; i < 4; i++)
            dst[(size_t)(n0 + ty + i * 8) * DD + k0 + tx] =
                __float2half_rn(tt[tx][ty + i * 8]);
    }
}

// ---------------- HMMA fp16 1-pass GEMM core (BK=64, SW128 swizzle, 3-stage) ----------------
#define BK 64
#define MAT 16384                    // 128 rows x 128B (64 fp16)
#define OFF_A 0
#define OFF_B (1 * MAT)
#define STAGE_BYTES (2 * MAT)        // 32768
#define NPIPE 3
#define GSMEM_TOTAL (NPIPE * STAGE_BYTES)  // 98304

__device__ __forceinline__ void load_stage(uint32_t sb,
                                           const __half* __restrict__ A,
                                           const __half* __restrict__ B,
                                           int m0, int n0, int kt, int tid) {
#pragma unroll
    for (int i = 0; i < 4; i++) {
        int idx = tid + i * 256;          // 0..1023
        int r = idx >> 3;                 // 0..127
        int c = idx & 7;                  // 16B chunk 0..7
        uint32_t so = (uint32_t)(r * 128 + ((c ^ (r & 7)) << 4));
        cp16(sb + OFF_A + so, A + (size_t)(m0 + r) * DD + kt + c * 8);
        cp16(sb + OFF_B + so, B + (size_t)(n0 + r) * DD + kt + c * 8);
    }
}

// OUT_MODE 0: fp32 C.  OUT_MODE 2: single fp16 (scale).
template <int OUT_MODE>
__device__ __forceinline__ void gemm_core(const __half* __restrict__ A,
                                          const __half* __restrict__ B,
                                          float* __restrict__ C,
                                          __half* __restrict__ Ch,
                                          float scale, int m0, int n0) {
    extern __shared__ char sm[];
    uint32_t sbase = smem_u32(sm);
    const int tid = threadIdx.x;
    const int wid = tid >> 5;
    const int lane = tid & 31;
    const int wm = wid & 3;
    const int wn = wid >> 2;

    const int g = lane >> 3;
    const int rr = lane & 7;
    const int rA = wm * 32 + (g & 1) * 8 + rr;
    const uint32_t aBase = (uint32_t)(rA * 128);
    const int swA = rA & 7;
    const int caBase = g >> 1;
    const int rB = wn * 64 + (g >> 1) * 8 + rr;
    const uint32_t bBase = (uint32_t)(rB * 128);
    const int swB = rB & 7;
    const int cbBase = g & 1;

    float acc[2][8][4];
#pragma unroll
    for (int mi = 0; mi < 2; mi++)
#pragma unroll
        for (int ni = 0; ni < 8; ni++)
#pragma unroll
            for (int j = 0; j < 4; j++) acc[mi][ni][j] = 0.0f;

    const int NST = DD / BK;   // 16
    load_stage(sbase + 0 * STAGE_BYTES, A, B, m0, n0, 0, tid);
    CP_COMMIT();
    load_stage(sbase + 1 * STAGE_BYTES, A, B, m0, n0, BK, tid);
    CP_COMMIT();

    int sidx = 0;
    for (int s = 0; s < NST; s++) {
        if (s < NST - 1) { CP_WAIT(1); } else { CP_WAIT(0); }
        __syncthreads();
        if (s + 2 < NST) {
            int nb = sidx + 2; if (nb >= 3) nb -= 3;
            load_stage(sbase + nb * STAGE_BYTES, A, B, m0, n0, (s + 2) * BK, tid);
            CP_COMMIT();
        }
        uint32_t sb = sbase + sidx * STAGE_BYTES;

#pragma unroll
        for (int kk = 0; kk < 4; kk++) {
            uint32_t ah[2][4], bf[4][4];
            const uint32_t aco = (uint32_t)(((caBase + 2 * kk) ^ swA) << 4);
            const uint32_t bco = (uint32_t)(((cbBase + 2 * kk) ^ swB) << 4);
#pragma unroll
            for (int mi = 0; mi < 2; mi++)
                ldm4(ah[mi], sb + OFF_A + aBase + (uint32_t)(mi * 2048) + aco);
#pragma unroll
            for (int np = 0; np < 4; np++)
                ldm4(bf[np], sb + OFF_B + bBase + (uint32_t)(np * 2048) + bco);
#pragma unroll
            for (int mi = 0; mi < 2; mi++)
#pragma unroll
                for (int ni = 0; ni < 8; ni++)
                    mma16816(acc[mi][ni], ah[mi], bf[ni >> 1][(ni & 1) * 2], bf[ni >> 1][(ni & 1) * 2 + 1]);
        }
        sidx++; if (sidx == 3) sidx = 0;
    }

    const int row_b = m0 + wm * 32 + (lane >> 2);
    const int col_b = n0 + wn * 64 + (lane & 3) * 2;
#pragma unroll
    for (int mi = 0; mi < 2; mi++)
#pragma unroll
        for (int ni = 0; ni < 8; ni++) {
            int row = row_b + mi * 16;
            int col = col_b + ni * 8;
            if (OUT_MODE == 0) {
                *(float2*)&C[(size_t)row * DD + col] =
                    make_float2(acc[mi][ni][0], acc[mi][ni][1]);
                *(float2*)&C[(size_t)(row + 8) * DD + col] =
                    make_float2(acc[mi][ni][2], acc[mi][ni][3]);
            } else {
#pragma unroll
                for (int rh = 0; rh < 2; rh++) {
                    float v0 = acc[mi][ni][rh * 2 + 0] * scale;
                    float v1 = acc[mi][ni][rh * 2 + 1] * scale;
                    *(uint32_t*)&Ch[(size_t)(row + rh * 8) * DD + col] = pack_h2(v0, v1);
                }
            }
        }
}

// ---------------- attention body (128-key stages, 64-key halves, gated) ----------------
#define QT 16384                     // Q: 128 x 64 fp16 = 128B rows
#define KT 16384                     // K tile: 128 rows x 128B
#define OFF_ST QT
#define STG (2 * KT)                 // 32768 (K, V)

__device__ __forceinline__ void kv_load(uint32_t stage, size_t gkv, int k0, int tid) {
#pragma unroll
    for (int i = 0; i < 8; i++) {
        int idx = tid + i * 256;          // 0..2047
        int tile = idx >> 10;             // 0=K, 1=V
        int rem = idx & 1023;
        int r = rem >> 3;                 // 0..127
        int c = rem & 7;
        const __half* src = tile ? g_v : g_k;
        cp16(stage + (uint32_t)(tile * KT + r * 128 + ((c ^ (r & 7)) << 4)),
             src + gkv + (size_t)(k0 + r) * DD + c * 8);
    }
}

__device__ __forceinline__ void attn_body(int abid) {
    extern __shared__ char sm[];
    uint32_t sb = smem_u32(sm);
    const int tid = threadIdx.x;
    const int wid = tid >> 5;
    const int lane = tid & 31;
    const int bh_idx = abid >> 4;         // 0..63
    const int b = bh_idx >> 4;
    const int h = bh_idx & 15;
    const int qx = abid & 15;
    const int q0 = (15 - qx) * 128;       // reversed: longest first
    const int mt0 = b << 4;

    // gate: Q tile and first KV tile ready
    if (tid == 0) {
        spin_until(&g_cnt[mt0 + (q0 >> 7)], 8);
        spin_until(&g_cnt[64 + mt0], 16);
    }
    __syncthreads();

    const size_t gq = (size_t)(b * SS + q0) * DD + h * HD;
    const size_t gkv = (size_t)(b * SS) * DD + h * HD;

    // load Q tile, swizzled
#pragma unroll
    for (int i = 0; i < 4; i++) {
        int r = i * 32 + (tid >> 3);
        int c = tid & 7;
        cp16(sb + (uint32_t)(r * 128 + ((c ^ (r & 7)) << 4)),
             g_q + gq + (size_t)r * DD + c * 8);
    }
    kv_load(sb + OFF_ST, gkv, 0, tid);
    CP_COMMIT();
    CP_WAIT(0);
    __syncthreads();

    // Q A-fragments
    uint32_t qh[4][4];
    {
        const int rQ = 16 * wid + (lane & 15);
        const int tQ = lane >> 4;
        const uint32_t qrow = sb + (uint32_t)(rQ * 128);
        const int sQ = rQ & 7;
#pragma unroll
        for (int q = 0; q < 4; q++)
            ldm4(qh[q], qrow + (uint32_t)(((tQ + 2 * q) ^ sQ) << 4));
    }

    const int rK = ((lane >> 4) << 3) + (lane & 7);
    const int tK = (lane >> 3) & 1;
    const int sK = rK & 7;
    const uint32_t kBase = (uint32_t)(rK * 128);
    const int rV = lane & 15;
    const int tV = lane >> 4;
    const int sV = rV & 7;
    const uint32_t vBase = (uint32_t)(rV * 128);

    float o[8][4];
#pragma unroll
    for (int nt = 0; nt < 8; nt++)
#pragma unroll
        for (int j = 0; j < 4; j++) o[nt][j] = 0.0f;
    float l0 = 0.0f, l1 = 0.0f;

    const int row0 = q0 + 16 * wid + (lane >> 2);
    const int row_min = q0 + 16 * wid;
    const int qrow_hi = q0 + 16 * wid + 15;
    const int ntiles = q0 / 128 + 1;     // 128-key stages

    for (int it = 0; it < ntiles; it++) {
        if (it + 1 < ntiles) {
            // gate next KV tile, then prefetch it
            if (tid == 0) spin_until(&g_cnt[64 + mt0 + it + 1], 16);
            __syncthreads();
            kv_load(sb + OFF_ST + ((it + 1) & 1) * STG, gkv, (it + 1) * 128, tid);
            CP_COMMIT();
            CP_WAIT(1);
        } else {
            CP_WAIT(0);
        }
        __syncthreads();
        const uint32_t stage = sb + OFF_ST + (it & 1) * STG;

#pragma unroll
        for (int h2 = 0; h2 < 2; h2++) {
            const int k0 = it * 128 + h2 * 64;
            if (k0 > qrow_hi) break;
            const uint32_t kst = stage + (uint32_t)(h2 * 8192);
            const uint32_t vst = stage + KT + (uint32_t)(h2 * 8192);

            // ---- S = Q K^T, single pass ----
            float s[8][4];
#pragma unroll
            for (int nt = 0; nt < 8; nt++)
#pragma unroll
                for (int j = 0; j < 4; j++) s[nt][j] = 0.0f;

#pragma unroll
            for (int q = 0; q < 4; q++) {
                const uint32_t kc = (uint32_t)((((2 * q) + tK) ^ sK) << 4);
#pragma unroll
                for (int pp = 0; pp < 2; pp++) {
                    uint32_t kf[2][4];
#pragma unroll
                    for (int p2 = 0; p2 < 2; p2++)
                        ldm4(kf[p2], kst + kBase + (uint32_t)((pp * 2 + p2) * 2048) + kc);
#pragma unroll
                    for (int p2 = 0; p2 < 2; p2++) {
                        int p = pp * 2 + p2;
                        mma16816(s[2 * p], qh[q], kf[p2][0], kf[p2][1]);
                        mma16816(s[2 * p + 1], qh[q], kf[p2][2], kf[p2][3]);
                    }
                }
            }

            // ---- causal mask ----
            if (k0 + 63 > row_min) {
#pragma unroll
                for (int nt = 0; nt < 8; nt++) {
                    int key = k0 + nt * 8 + (lane & 3) * 2;
#pragma unroll
                    for (int j = 0; j < 4; j++) {
                        int r = row0 + (j >> 1) * 8;
                        if (key + (j & 1) > r) s[nt][j] = -1e30f;
                    }
                }
            }

            // ---- no-max softmax: P = 2^s ----
#pragma unroll
            for (int nt = 0; nt < 8; nt++) {
                s[nt][0] = ex2f(s[nt][0]);
                s[nt][1] = ex2f(s[nt][1]);
                s[nt][2] = ex2f(s[nt][2]);
                s[nt][3] = ex2f(s[nt][3]);
                l0 += s[nt][0] + s[nt][1];
                l1 += s[nt][2] + s[nt][3];
            }

            // ---- PV, single pass ----
#pragma unroll
            for (int kk = 0; kk < 4; kk++) {
                uint32_t pah[4];
                pah[0] = pack_h2(s[2 * kk][0], s[2 * kk][1]);
                pah[1] = pack_h2(s[2 * kk][2], s[2 * kk][3]);
                pah[2] = pack_h2(s[2 * kk + 1][0], s[2 * kk + 1][1]);
                pah[3] = pack_h2(s[2 * kk + 1][2], s[2 * kk + 1][3]);
                const uint32_t vrow = vst + vBase + (uint32_t)(kk * 2048);
#pragma unroll
                for (int uu = 0; uu < 2; uu++) {
                    uint32_t vf[2][4];
#pragma unroll
                    for (int u2 = 0; u2 < 2; u2++)
                        ldm4t(vf[u2], vrow + (uint32_t)((((2 * (uu * 2 + u2)) + tV) ^ sV) << 4));
#pragma unroll
                    for (int u2 = 0; u2 < 2; u2++) {
                        int u = uu * 2 + u2;
                        mma16816(o[2 * u], pah, vf[u2][0], vf[u2][1]);
                        mma16816(o[2 * u + 1], pah, vf[u2][2], vf[u2][3]);
                    }
                }
            }
        }
        __syncthreads();
    }

    // ---- finalize: normalize, fp16 out ----
    l0 += __shfl_xor_sync(0xffffffffu, l0, 1);
    l0 += __shfl_xor_sync(0xffffffffu, l0, 2);
    l1 += __shfl_xor_sync(0xffffffffu, l1, 1);
    l1 += __shfl_xor_sync(0xffffffffu, l1, 2);
    float inv0 = 1.0f / l0;
    float inv1 = 1.0f / l1;

    const int grow0 = b * SS + q0 + 16 * wid + (lane >> 2);
    const int gcol = h * HD + (lane & 3) * 2;
#pragma unroll
    for (int nt = 0; nt < 8; nt++) {
#pragma unroll
        for (int rh = 0; rh < 2; rh++) {
            float inv = rh ? inv1 : inv0;
            float v0 = o[nt][rh * 2 + 0] * inv;
            float v1 = o[nt][rh * 2 + 1] * inv;
            size_t off = (size_t)(grow0 + rh * 8) * DD + gcol + nt * 8;
            *(uint32_t*)&g_oa[off] = pack_h2(v0, v1);
        }
    }

    // ---- publish completion for this (b, qblock) m-tile ----
    __threadfence();
    __syncthreads();
    if (tid == 0)
        atomicAdd(&g_cnt[128 + mt0 + (q0 >> 7)], 1);
}

// ---------------- mega kernel: QKV + attention + out-projection ----------------
// bids [0,512): Q tiles. [512,1536): K/V interleaved per m-tile.
// bids [1536,2560): attention. [2560,3072): out-proj.
__global__ void __launch_bounds__(256, 2)
mega_kernel(float* __restrict__ out) {
    const int bid = blockIdx.x;
    if (bid < 1536) {
        int z, mt, n;
        if (bid < 512) { z = 0; mt = bid >> 3; n = bid & 7; }
        else {
            int t = bid - 512;            // 0..1023
            mt = t >> 4;
            int sub = t & 15;
            z = 1 + (sub >> 3);
            n = sub & 7;
        }
        const int m0 = mt * 128, n0 = n * 128;
        if (z == 0)      gemm_core<2>(g_x, g_wq, nullptr, g_q, QSCALE, m0, n0);
        else if (z == 1) gemm_core<2>(g_x, g_wk, nullptr, g_k, 1.0f, m0, n0);
        else             gemm_core<2>(g_x, g_wv, nullptr, g_v, 1.0f, m0, n0);
        __threadfence();
        __syncthreads();
        if (threadIdx.x == 0)
            atomicAdd(&g_cnt[(z == 0 ? 0 : 64) + mt], 1);
    } else if (bid < 2560) {
        attn_body(bid - 1536);
    } else {
        const int obid = bid - 2560;
        const int mt = obid >> 3;               // m-tile 0..63
        const int m0 = mt * 128;
        const int n0 = (obid & 7) * 128;
        if (threadIdx.x == 0) spin_until(&g_cnt[128 + mt], 16);
        __syncthreads();
        gemm_core<0>(g_oa, g_wo, out, nullptr, 1.0f, m0, n0);
    }
}

// ---------------- launch ----------------
extern "C" void kernel_launch(void* const* d_in, const int* in_sizes, int n_in,
                              void* d_out, int out_size) {
    const float* x  = (const float*)d_in[0];
    const float* Wq = (const float*)d_in[1];
    const float* Wk = (const float*)d_in[2];
    const float* Wv = (const float*)d_in[3];
    const float* Wo = (const float*)d_in[4];
    float* out = (float*)d_out;

    cudaFuncSetAttribute(mega_kernel,
                         cudaFuncAttributeMaxDynamicSharedMemorySize, GSMEM_TOTAL);

    prep_kernel<<<12288, 256>>>(x, Wq, Wk, Wv, Wo);
    mega_kernel<<<3072, 256, GSMEM_TOTAL>>>(out);
}